// round 1
// baseline (speedup 1.0000x reference)
#include <cuda_runtime.h>

#define VOCAB 10000
#define EMBED 100
#define SEQ   80
#define UNITS 64
#define BATCH 16384
#define HSTRIDE 65   // padded stride for per-row hidden state in smem (conflict-free)

// Scratch: precomputed input projection xproj[v][u] = b1[u] + emb[v,:] @ Wx1[:,u]
__device__ float g_xproj[VOCAB * UNITS];

// ---------------------------------------------------------------------------
// Kernel A: build xproj table (10000 x 64). 4 vocab rows per 256-thread block.
// ---------------------------------------------------------------------------
__global__ void build_xproj_kernel(const float* __restrict__ emb,
                                   const float* __restrict__ Wx1,
                                   const float* __restrict__ b1) {
    __shared__ float se[4 * EMBED];
    const int v0  = blockIdx.x * 4;
    const int tid = threadIdx.x;
    for (int i = tid; i < 4 * EMBED; i += 256)
        se[i] = emb[v0 * EMBED + i];
    __syncthreads();

    const int vl = tid >> 6;     // 0..3 local vocab row
    const int u  = tid & 63;     // output unit
    const float* er = se + vl * EMBED;
    float a0 = 0.f, a1 = 0.f;
#pragma unroll
    for (int e = 0; e < EMBED; e += 2) {
        a0 += er[e]     * Wx1[e * UNITS + u];
        a1 += er[e + 1] * Wx1[(e + 1) * UNITS + u];
    }
    g_xproj[(v0 + vl) * UNITS + u] = b1[u] + a0 + a1;
}

// Accurate-enough tanh: 1 - 2/(exp(2x)+1).  EX2+RCP based, rel err ~4e-6 for
// the small |x| this net produces (values ~0.03), far inside the 1e-3 budget.
__device__ __forceinline__ float fast_tanh(float x) {
    float e = __expf(2.0f * x);
    return 1.0f - __fdividef(2.0f, e + 1.0f);
}

// ---------------------------------------------------------------------------
// Kernel B: fused 2-layer RNN sweep + sigmoid head.
// One thread = one batch row. Hidden state in padded smem (dynamically
// indexable private storage); acc[64] in registers. Weights in smem,
// broadcast LDS.128 (1 load per 4 FFMA).
// ---------------------------------------------------------------------------
__global__ void __launch_bounds__(128, 1)
rnn_fused_kernel(const int*   __restrict__ tokens,
                 const float* __restrict__ Wh1,
                 const float* __restrict__ Wx2,
                 const float* __restrict__ Wh2,
                 const float* __restrict__ b2,
                 const float* __restrict__ Wd,
                 const float* __restrict__ bd,
                 float*       __restrict__ out) {
    extern __shared__ float sm[];
    float* h1s  = sm;                          // 128 * 65
    float* h2s  = sm + 128 * HSTRIDE;          // 128 * 65
    float* sWh1 = sm + 2 * 128 * HSTRIDE;      // 4096
    float* sWx2 = sWh1 + UNITS * UNITS;        // 4096
    float* sWh2 = sWx2 + UNITS * UNITS;        // 4096
    float* sb2  = sWh2 + UNITS * UNITS;        // 64  (16B-aligned offset)
    float* sWd  = sb2 + UNITS;                 // 64

    const int tid = threadIdx.x;
    for (int i = tid; i < UNITS * UNITS; i += 128) {
        sWh1[i] = Wh1[i];
        sWx2[i] = Wx2[i];
        sWh2[i] = Wh2[i];
    }
    if (tid < UNITS) { sb2[tid] = b2[tid]; sWd[tid] = Wd[tid]; }

    float* myh1 = h1s + tid * HSTRIDE;
    float* myh2 = h2s + tid * HSTRIDE;
#pragma unroll
    for (int k = 0; k < UNITS; k++) { myh1[k] = 0.f; myh2[k] = 0.f; }
    __syncthreads();

    const int row = blockIdx.x * 128 + tid;
    const int* trow = tokens + row * SEQ;

    float acc[UNITS];

    for (int t = 0; t < SEQ; t++) {
        const int tok = trow[t];
        const float4* xp = reinterpret_cast<const float4*>(g_xproj + tok * UNITS);

        // acc = xproj (already includes b1)
#pragma unroll
        for (int j4 = 0; j4 < 16; j4++) {
            float4 v = xp[j4];
            acc[4*j4+0] = v.x; acc[4*j4+1] = v.y;
            acc[4*j4+2] = v.z; acc[4*j4+3] = v.w;
        }

        // acc += h1 @ Wh1
#pragma unroll 2
        for (int k = 0; k < UNITS; k++) {
            const float hk = myh1[k];
            const float4* wr = reinterpret_cast<const float4*>(sWh1 + k * UNITS);
#pragma unroll
            for (int j4 = 0; j4 < 16; j4++) {
                float4 w = wr[j4];
                acc[4*j4+0] += hk * w.x; acc[4*j4+1] += hk * w.y;
                acc[4*j4+2] += hk * w.z; acc[4*j4+3] += hk * w.w;
            }
        }
#pragma unroll
        for (int j = 0; j < UNITS; j++)
            myh1[j] = fast_tanh(acc[j]);

        // layer 2: acc = b2 + h1_new @ Wx2 + h2 @ Wh2
        {
            const float4* bb = reinterpret_cast<const float4*>(sb2);
#pragma unroll
            for (int j4 = 0; j4 < 16; j4++) {
                float4 v = bb[j4];
                acc[4*j4+0] = v.x; acc[4*j4+1] = v.y;
                acc[4*j4+2] = v.z; acc[4*j4+3] = v.w;
            }
        }
#pragma unroll 2
        for (int k = 0; k < UNITS; k++) {
            const float ak = myh1[k];
            const float bk = myh2[k];
            const float4* wa = reinterpret_cast<const float4*>(sWx2 + k * UNITS);
            const float4* wb = reinterpret_cast<const float4*>(sWh2 + k * UNITS);
#pragma unroll
            for (int j4 = 0; j4 < 16; j4++) {
                float4 a = wa[j4], b = wb[j4];
                acc[4*j4+0] += ak * a.x + bk * b.x;
                acc[4*j4+1] += ak * a.y + bk * b.y;
                acc[4*j4+2] += ak * a.z + bk * b.z;
                acc[4*j4+3] += ak * a.w + bk * b.w;
            }
        }
#pragma unroll
        for (int j = 0; j < UNITS; j++)
            myh2[j] = fast_tanh(acc[j]);
    }

    // head: sigmoid(h2 @ Wd + bd)
    float z = bd[0];
#pragma unroll
    for (int j = 0; j < UNITS; j++)
        z += myh2[j] * sWd[j];
    out[row] = 1.0f / (1.0f + expf(-z));
}

// ---------------------------------------------------------------------------
extern "C" void kernel_launch(void* const* d_in, const int* in_sizes, int n_in,
                              void* d_out, int out_size) {
    const int*   tokens = (const int*)  d_in[0];
    const float* emb    = (const float*)d_in[1];
    const float* Wx1    = (const float*)d_in[2];
    const float* Wh1    = (const float*)d_in[3];
    const float* b1     = (const float*)d_in[4];
    const float* Wx2    = (const float*)d_in[5];
    const float* Wh2    = (const float*)d_in[6];
    const float* b2     = (const float*)d_in[7];
    const float* Wd     = (const float*)d_in[8];
    const float* bd     = (const float*)d_in[9];
    float* out = (float*)d_out;

    build_xproj_kernel<<<VOCAB / 4, 256>>>(emb, Wx1, b1);

    const int smem_bytes = (2 * 128 * HSTRIDE + 3 * UNITS * UNITS + 2 * UNITS)
                           * (int)sizeof(float);
    cudaFuncSetAttribute(rnn_fused_kernel,
                         cudaFuncAttributeMaxDynamicSharedMemorySize, smem_bytes);
    rnn_fused_kernel<<<BATCH / 128, 128, smem_bytes>>>(
        tokens, Wh1, Wx2, Wh2, b2, Wd, bd, out);
}

// round 3
// speedup vs baseline: 3.5879x; 3.5879x over previous
#include <cuda_runtime.h>
#include <cuda_bf16.h>
#include <cstdint>

#define VOCAB 10000
#define EMBED 100
#define SEQ   80
#define UNITS 64
#define BATCH 16384
#define MROWS 128          // batch rows per CTA
#define XS    68           // xproj smem row stride (floats) — conflict-spread
#define TKS   81           // token smem row stride (ints)  — conflict-free

// xproj[v][u] = b1[u] + emb[v,:] @ Wx1[:,u]   (fp32, 2.56 MB, L2-resident)
__device__ float g_xproj[VOCAB * UNITS];

// ---------------------------------------------------------------------------
// helpers
// ---------------------------------------------------------------------------
__device__ __forceinline__ uint32_t smem_u32(const void* p) {
    uint32_t a;
    asm("{ .reg .u64 t; cvta.to.shared.u64 t, %1; cvt.u32.u64 %0, t; }" : "=r"(a) : "l"(p));
    return a;
}
#define SWZ(off) ((uint32_t)(off) ^ ((((uint32_t)(off)) >> 3) & 0x70))

__device__ __forceinline__ float tanh_fast(float x) {
    float r; asm("tanh.approx.f32 %0, %1;" : "=f"(r) : "f"(x)); return r;
}
__device__ __forceinline__ uint32_t pack_bf16(float lo, float hi) {
    uint32_t r; asm("cvt.rn.bf16x2.f32 %0, %1, %2;" : "=r"(r) : "f"(hi), "f"(lo)); return r;
}
__device__ __forceinline__ float2 unpk_bf16(uint32_t u) {
    __nv_bfloat162 b = *reinterpret_cast<__nv_bfloat162*>(&u);
    return __bfloat1622float2(b);
}

#define LDSM_X4(r0, r1, r2, r3, addr)                                       \
    asm volatile("ldmatrix.sync.aligned.m8n8.x4.shared.b16 {%0,%1,%2,%3}, [%4];" \
                 : "=r"(r0), "=r"(r1), "=r"(r2), "=r"(r3) : "r"(addr))

#define MMA_BF16(ac, A, b0, b1)                                             \
    asm volatile("mma.sync.aligned.m16n8k16.row.col.f32.bf16.bf16.f32 "     \
                 "{%0,%1,%2,%3}, {%4,%5,%6,%7}, {%8,%9}, {%0,%1,%2,%3};"    \
                 : "+f"((ac)[0]), "+f"((ac)[1]), "+f"((ac)[2]), "+f"((ac)[3]) \
                 : "r"((A)[0]), "r"((A)[1]), "r"((A)[2]), "r"((A)[3]),      \
                   "r"(b0), "r"(b1))

// ---------------------------------------------------------------------------
// Kernel A: build xproj table (unchanged — correct, ~10 us)
// ---------------------------------------------------------------------------
__global__ void build_xproj_kernel(const float* __restrict__ emb,
                                   const float* __restrict__ Wx1,
                                   const float* __restrict__ b1) {
    __shared__ float se[4 * EMBED];
    const int v0  = blockIdx.x * 4;
    const int tid = threadIdx.x;
    for (int i = tid; i < 4 * EMBED; i += 256)
        se[i] = emb[v0 * EMBED + i];
    __syncthreads();
    const int vl = tid >> 6;
    const int u  = tid & 63;
    const float* er = se + vl * EMBED;
    float a0 = 0.f, a1 = 0.f;
#pragma unroll
    for (int e = 0; e < EMBED; e += 2) {
        a0 += er[e]     * Wx1[e * UNITS + u];
        a1 += er[e + 1] * Wx1[(e + 1) * UNITS + u];
    }
    g_xproj[(v0 + vl) * UNITS + u] = b1[u] + a0 + a1;
}

// ---------------------------------------------------------------------------
// smem layout (byte offsets from 1024-aligned base)
// ---------------------------------------------------------------------------
#define OFF_H1   0                                  // 128 x 128B bf16 tile (SW128)
#define OFF_H2   16384                              // 128 x 128B bf16 tile
#define OFF_XSM  32768                              // 128 x 68 fp32
#define OFF_TOK  (OFF_XSM + MROWS * XS * 4)         // 128 x 81 int
#define OFF_WD   (OFF_TOK + MROWS * TKS * 4)        // 64 fp32
#define SMEM_NEED (OFF_WD + 256 + 1024)

// ---------------------------------------------------------------------------
// Kernel B: mma.sync-based fused 2-layer RNN. 1 CTA = 128 rows, 4 warps.
// Warp w computes output cols [16w, 16w+16) of every 128x64 GEMM.
// Weights live in registers as B-fragments (persistent). h tiles bf16 in smem.
// ---------------------------------------------------------------------------
__global__ void __launch_bounds__(128, 1)
rnn_mma_kernel(const int*   __restrict__ tokens,
               const float* __restrict__ Wh1,
               const float* __restrict__ Wx2,
               const float* __restrict__ Wh2,
               const float* __restrict__ b2,
               const float* __restrict__ Wd,
               const float* __restrict__ bd,
               float*       __restrict__ out) {
    extern __shared__ char dynsmem[];
    char* smem = (char*)(((uintptr_t)dynsmem + 1023) & ~(uintptr_t)1023);
    const uint32_t sb = smem_u32(smem);
    float* xs = (float*)(smem + OFF_XSM);
    int*   stok = (int*)(smem + OFF_TOK);
    float* sWd = (float*)(smem + OFF_WD);

    const int tid  = threadIdx.x;
    const int lane = tid & 31;
    const int wid  = tid >> 5;
    const int gid  = lane >> 2;     // 0..7
    const int tig  = lane & 3;      // 0..3
    const int n0   = wid * 16;      // this warp's output-column base
    const int m0   = blockIdx.x * MROWS;

    // ---- persistent B-fragments (loaded once from global fp32) ----
    // m16n8k16 .col B frag: b0 = {B[k][n], B[k+1][n]}, b1 = {B[k+8][n], B[k+9][n]}
    // with n = n0 + nt*8 + gid, k = kt*16 + 2*tig.  B[k][n] == W[k*64+n].
    uint32_t B1[2][4][2], BX2[2][4][2], BH2[2][4][2];
#pragma unroll
    for (int nt = 0; nt < 2; nt++)
#pragma unroll
        for (int kt = 0; kt < 4; kt++) {
            const int n = n0 + nt * 8 + gid;
            const int k = kt * 16 + tig * 2;
            B1 [nt][kt][0] = pack_bf16(Wh1[k * 64 + n],       Wh1[(k + 1) * 64 + n]);
            B1 [nt][kt][1] = pack_bf16(Wh1[(k + 8) * 64 + n], Wh1[(k + 9) * 64 + n]);
            BX2[nt][kt][0] = pack_bf16(Wx2[k * 64 + n],       Wx2[(k + 1) * 64 + n]);
            BX2[nt][kt][1] = pack_bf16(Wx2[(k + 8) * 64 + n], Wx2[(k + 9) * 64 + n]);
            BH2[nt][kt][0] = pack_bf16(Wh2[k * 64 + n],       Wh2[(k + 1) * 64 + n]);
            BH2[nt][kt][1] = pack_bf16(Wh2[(k + 8) * 64 + n], Wh2[(k + 9) * 64 + n]);
        }
    // b2 values this thread needs in epilogue2 (C-frag cols)
    float b2v[2][2];
#pragma unroll
    for (int nt = 0; nt < 2; nt++) {
        b2v[nt][0] = b2[n0 + nt * 8 + tig * 2];
        b2v[nt][1] = b2[n0 + nt * 8 + tig * 2 + 1];
    }

    // zero h tiles (h0 = 0)
    for (int i = tid; i < 32768 / 4; i += 128)
        ((uint32_t*)(smem + OFF_H1))[i] = 0;
    // tokens -> smem, padded stride
    {
        const int* gtok = tokens + m0 * SEQ;
        for (int i = tid; i < MROWS * SEQ; i += 128)
            stok[(i / SEQ) * TKS + (i % SEQ)] = gtok[i];
    }
    if (tid < UNITS) sWd[tid] = Wd[tid];
    __syncthreads();

    const int arow   = lane & 15;
    const int achunk = lane >> 4;
    float acc[8][2][4];

    for (int t = 0; t < SEQ; t++) {
        // ---- stage xproj row for my batch row (L2 gather -> smem) ----
        {
            const int tok = stok[tid * TKS + t];
            const float4* xp  = (const float4*)(g_xproj + tok * UNITS);
            float4*       dst = (float4*)(xs + tid * XS);
#pragma unroll
            for (int i = 0; i < 16; i++) dst[i] = xp[i];
        }

        // ---- MMA1: acc = h1 @ Wh1  (K=64) ----
#pragma unroll
        for (int mt = 0; mt < 8; mt++)
#pragma unroll
            for (int nt = 0; nt < 2; nt++)
#pragma unroll
                for (int c = 0; c < 4; c++) acc[mt][nt][c] = 0.f;
#pragma unroll
        for (int kt = 0; kt < 4; kt++) {
            uint32_t A[8][4];
#pragma unroll
            for (int mt = 0; mt < 8; mt++) {
                uint32_t rel = (uint32_t)((mt * 16 + arow) * 128 + kt * 32 + achunk * 16);
                LDSM_X4(A[mt][0], A[mt][1], A[mt][2], A[mt][3], sb + OFF_H1 + SWZ(rel));
            }
#pragma unroll
            for (int mt = 0; mt < 8; mt++) {
                MMA_BF16(acc[mt][0], A[mt], B1[0][kt][0], B1[0][kt][1]);
                MMA_BF16(acc[mt][1], A[mt], B1[1][kt][0], B1[1][kt][1]);
            }
        }
        __syncthreads();   // xs staged by all; all warps done reading h1

        // ---- epilogue 1: h1 = tanh(acc + xproj) ----
#pragma unroll
        for (int mt = 0; mt < 8; mt++) {
            const int r0 = mt * 16 + gid;
#pragma unroll
            for (int nt = 0; nt < 2; nt++) {
                const int col = n0 + nt * 8 + tig * 2;
                float2 xa = *(float2*)(xs + r0 * XS + col);
                float2 xb = *(float2*)(xs + (r0 + 8) * XS + col);
                float h0 = tanh_fast(acc[mt][nt][0] + xa.x);
                float h1 = tanh_fast(acc[mt][nt][1] + xa.y);
                float h2 = tanh_fast(acc[mt][nt][2] + xb.x);
                float h3 = tanh_fast(acc[mt][nt][3] + xb.y);
                *(uint32_t*)(smem + OFF_H1 + SWZ(r0 * 128 + col * 2))       = pack_bf16(h0, h1);
                *(uint32_t*)(smem + OFF_H1 + SWZ((r0 + 8) * 128 + col * 2)) = pack_bf16(h2, h3);
            }
        }
        __syncthreads();   // h1 ready

        // ---- MMA2: acc = h1 @ Wx2 + h2 @ Wh2  (K=64+64) ----
#pragma unroll
        for (int mt = 0; mt < 8; mt++)
#pragma unroll
            for (int nt = 0; nt < 2; nt++)
#pragma unroll
                for (int c = 0; c < 4; c++) acc[mt][nt][c] = 0.f;
#pragma unroll
        for (int kt = 0; kt < 4; kt++) {
            uint32_t A[8][4];
#pragma unroll
            for (int mt = 0; mt < 8; mt++) {
                uint32_t rel = (uint32_t)((mt * 16 + arow) * 128 + kt * 32 + achunk * 16);
                LDSM_X4(A[mt][0], A[mt][1], A[mt][2], A[mt][3], sb + OFF_H1 + SWZ(rel));
            }
#pragma unroll
            for (int mt = 0; mt < 8; mt++) {
                MMA_BF16(acc[mt][0], A[mt], BX2[0][kt][0], BX2[0][kt][1]);
                MMA_BF16(acc[mt][1], A[mt], BX2[1][kt][0], BX2[1][kt][1]);
            }
        }
#pragma unroll
        for (int kt = 0; kt < 4; kt++) {
            uint32_t A[8][4];
#pragma unroll
            for (int mt = 0; mt < 8; mt++) {
                uint32_t rel = (uint32_t)((mt * 16 + arow) * 128 + kt * 32 + achunk * 16);
                LDSM_X4(A[mt][0], A[mt][1], A[mt][2], A[mt][3], sb + OFF_H2 + SWZ(rel));
            }
#pragma unroll
            for (int mt = 0; mt < 8; mt++) {
                MMA_BF16(acc[mt][0], A[mt], BH2[0][kt][0], BH2[0][kt][1]);
                MMA_BF16(acc[mt][1], A[mt], BH2[1][kt][0], BH2[1][kt][1]);
            }
        }
        __syncthreads();   // all warps done reading h2

        // ---- epilogue 2: h2 = tanh(acc + b2) ----
#pragma unroll
        for (int mt = 0; mt < 8; mt++) {
            const int r0 = mt * 16 + gid;
#pragma unroll
            for (int nt = 0; nt < 2; nt++) {
                const int col = n0 + nt * 8 + tig * 2;
                float h0 = tanh_fast(acc[mt][nt][0] + b2v[nt][0]);
                float h1 = tanh_fast(acc[mt][nt][1] + b2v[nt][1]);
                float h2 = tanh_fast(acc[mt][nt][2] + b2v[nt][0]);
                float h3 = tanh_fast(acc[mt][nt][3] + b2v[nt][1]);
                *(uint32_t*)(smem + OFF_H2 + SWZ(r0 * 128 + col * 2))       = pack_bf16(h0, h1);
                *(uint32_t*)(smem + OFF_H2 + SWZ((r0 + 8) * 128 + col * 2)) = pack_bf16(h2, h3);
            }
        }
        __syncthreads();   // h2 ready for next step / head
    }

    // ---- head: out = sigmoid(h2 . Wd + bd), thread tid owns row tid ----
    float z = 0.f;
#pragma unroll
    for (int c = 0; c < 8; c++) {
        uint4 u = *(uint4*)(smem + OFF_H2 + SWZ(tid * 128 + c * 16));
        float2 p;
        p = unpk_bf16(u.x); z += p.x * sWd[c * 8 + 0] + p.y * sWd[c * 8 + 1];
        p = unpk_bf16(u.y); z += p.x * sWd[c * 8 + 2] + p.y * sWd[c * 8 + 3];
        p = unpk_bf16(u.z); z += p.x * sWd[c * 8 + 4] + p.y * sWd[c * 8 + 5];
        p = unpk_bf16(u.w); z += p.x * sWd[c * 8 + 6] + p.y * sWd[c * 8 + 7];
    }
    out[m0 + tid] = 1.0f / (1.0f + __expf(-(z + bd[0])));
}

// ---------------------------------------------------------------------------
extern "C" void kernel_launch(void* const* d_in, const int* in_sizes, int n_in,
                              void* d_out, int out_size) {
    const int*   tokens = (const int*)  d_in[0];
    const float* emb    = (const float*)d_in[1];
    const float* Wx1    = (const float*)d_in[2];
    const float* Wh1    = (const float*)d_in[3];
    const float* b1     = (const float*)d_in[4];
    const float* Wx2    = (const float*)d_in[5];
    const float* Wh2    = (const float*)d_in[6];
    const float* b2     = (const float*)d_in[7];
    const float* Wd     = (const float*)d_in[8];
    const float* bd     = (const float*)d_in[9];
    float* out = (float*)d_out;

    build_xproj_kernel<<<VOCAB / 4, 256>>>(emb, Wx1, b1);

    cudaFuncSetAttribute(rnn_mma_kernel,
                         cudaFuncAttributeMaxDynamicSharedMemorySize, SMEM_NEED);
    rnn_mma_kernel<<<BATCH / MROWS, 128, SMEM_NEED>>>(
        tokens, Wh1, Wx2, Wh2, b2, Wd, bd, out);
}

// round 4
// speedup vs baseline: 5.3544x; 1.4923x over previous
#include <cuda_runtime.h>
#include <cuda_bf16.h>
#include <cstdint>

#define VOCAB 10000
#define EMBED 100
#define SEQ   80
#define UNITS 64
#define BATCH 16384
#define MROWS 128          // batch rows per CTA
#define WR    16           // rows per warp (8 warps)
#define XS    68           // xproj smem row stride (floats)
#define TKS   81           // token smem row stride (ints)

// xproj[v][u] = b1[u] + emb[v,:] @ Wx1[:,u]   (fp32, 2.56 MB, L2-resident)
__device__ float g_xproj[VOCAB * UNITS];

// ---------------------------------------------------------------------------
// helpers
// ---------------------------------------------------------------------------
__device__ __forceinline__ uint32_t smem_u32(const void* p) {
    uint32_t a;
    asm("{ .reg .u64 t; cvta.to.shared.u64 t, %1; cvt.u32.u64 %0, t; }" : "=r"(a) : "l"(p));
    return a;
}
#define SWZ(off) ((uint32_t)(off) ^ ((((uint32_t)(off)) >> 3) & 0x70))

__device__ __forceinline__ float tanh_fast(float x) {
    float r; asm("tanh.approx.f32 %0, %1;" : "=f"(r) : "f"(x)); return r;
}
__device__ __forceinline__ uint32_t pack_bf16(float lo, float hi) {
    uint32_t r; asm("cvt.rn.bf16x2.f32 %0, %1, %2;" : "=r"(r) : "f"(hi), "f"(lo)); return r;
}
__device__ __forceinline__ float2 unpk_bf16(uint32_t u) {
    __nv_bfloat162 b = *reinterpret_cast<__nv_bfloat162*>(&u);
    return __bfloat1622float2(b);
}

#define LDSM_X4(r0, r1, r2, r3, addr)                                       \
    asm volatile("ldmatrix.sync.aligned.m8n8.x4.shared.b16 {%0,%1,%2,%3}, [%4];" \
                 : "=r"(r0), "=r"(r1), "=r"(r2), "=r"(r3) : "r"(addr))

#define MMA_BF16(ac, A, b0, b1)                                             \
    asm volatile("mma.sync.aligned.m16n8k16.row.col.f32.bf16.bf16.f32 "     \
                 "{%0,%1,%2,%3}, {%4,%5,%6,%7}, {%8,%9}, {%0,%1,%2,%3};"    \
                 : "+f"((ac)[0]), "+f"((ac)[1]), "+f"((ac)[2]), "+f"((ac)[3]) \
                 : "r"((A)[0]), "r"((A)[1]), "r"((A)[2]), "r"((A)[3]),      \
                   "r"(b0), "r"(b1))

// ---------------------------------------------------------------------------
// Kernel A: build xproj table
// ---------------------------------------------------------------------------
__global__ void build_xproj_kernel(const float* __restrict__ emb,
                                   const float* __restrict__ Wx1,
                                   const float* __restrict__ b1) {
    __shared__ float se[4 * EMBED];
    const int v0  = blockIdx.x * 4;
    const int tid = threadIdx.x;
    for (int i = tid; i < 4 * EMBED; i += 256)
        se[i] = emb[v0 * EMBED + i];
    __syncthreads();
    const int vl = tid >> 6;
    const int u  = tid & 63;
    const float* er = se + vl * EMBED;
    float a0 = 0.f, a1 = 0.f;
#pragma unroll
    for (int e = 0; e < EMBED; e += 2) {
        a0 += er[e]     * Wx1[e * UNITS + u];
        a1 += er[e + 1] * Wx1[(e + 1) * UNITS + u];
    }
    g_xproj[(v0 + vl) * UNITS + u] = b1[u] + a0 + a1;
}

// ---------------------------------------------------------------------------
// smem layout (byte offsets from 1024-aligned base)
// ---------------------------------------------------------------------------
#define OFF_H1   0                                  // 128 x 128B bf16 (SW128)
#define OFF_H2   16384                              // 128 x 128B bf16
#define OFF_W1   32768                              // Wh1^T [n][k] bf16 SW128, 8KB
#define OFF_WX2  40960
#define OFF_WH2  49152
#define OFF_XSM  57344                              // 128 x 68 fp32
#define OFF_TOK  (OFF_XSM + MROWS * XS * 4)         // 128 x 81 int
#define OFF_B2   (OFF_TOK + MROWS * TKS * 4)
#define OFF_WD   (OFF_B2 + 256)
#define SMEM_NEED (OFF_WD + 256 + 1024)

// C[16x64] += A[16x64] @ B[64x64]; A-tile rows folded into aBase (wrow*128).
__device__ __forceinline__ void gemm16x64(uint32_t aBase, uint32_t bBase,
                                          int lane, float (&acc)[8][4]) {
    const uint32_t aRel0 = (uint32_t)((lane & 15) * 128 + (lane >> 4) * 16);
    const uint32_t bRow  = (uint32_t)(((lane >> 4) << 3) | (lane & 7));
    const uint32_t bKo   = (uint32_t)(((lane >> 3) & 1) << 3);
#pragma unroll
    for (int kt = 0; kt < 4; kt++) {
        uint32_t A[4];
        LDSM_X4(A[0], A[1], A[2], A[3], aBase + SWZ(aRel0 + kt * 32));
        uint32_t B[4][4];
#pragma unroll
        for (int np = 0; np < 4; np++) {
            uint32_t bRel = (np * 16 + bRow) * 128 + (kt * 16 + bKo) * 2;
            LDSM_X4(B[np][0], B[np][1], B[np][2], B[np][3], bBase + SWZ(bRel));
        }
#pragma unroll
        for (int np = 0; np < 4; np++) {
            MMA_BF16(acc[2 * np],     A, B[np][0], B[np][1]);
            MMA_BF16(acc[2 * np + 1], A, B[np][2], B[np][3]);
        }
    }
}

// ---------------------------------------------------------------------------
// Kernel B: 8 warps x 16 rows, barrier-free recurrence loop.
// ---------------------------------------------------------------------------
__global__ void __launch_bounds__(256, 1)
rnn_mma_kernel(const int*   __restrict__ tokens,
               const float* __restrict__ Wh1,
               const float* __restrict__ Wx2,
               const float* __restrict__ Wh2,
               const float* __restrict__ b2,
               const float* __restrict__ Wd,
               const float* __restrict__ bd,
               float*       __restrict__ out) {
    extern __shared__ char dynsmem[];
    char* smem = (char*)(((uintptr_t)dynsmem + 1023) & ~(uintptr_t)1023);
    const uint32_t sb = smem_u32(smem);
    float* xs   = (float*)(smem + OFF_XSM);
    int*   stok = (int*)(smem + OFF_TOK);
    float* sB2  = (float*)(smem + OFF_B2);
    float* sWd  = (float*)(smem + OFF_WD);

    const int tid  = threadIdx.x;
    const int lane = tid & 31;
    const int wid  = tid >> 5;
    const int gid  = lane >> 2;
    const int tig  = lane & 3;
    const int wrow = wid * WR;               // warp's first row
    const int m0   = blockIdx.x * MROWS;

    // ---- init: weight^T tiles [n][k] bf16 SW128, zero h, tokens, vectors ----
    for (int i = tid; i < UNITS * UNITS; i += 256) {
        int n = i >> 6, k = i & 63;
        uint32_t so = SWZ(n * 128 + k * 2);
        *(__nv_bfloat16*)(smem + OFF_W1  + so) = __float2bfloat16(Wh1[k * 64 + n]);
        *(__nv_bfloat16*)(smem + OFF_WX2 + so) = __float2bfloat16(Wx2[k * 64 + n]);
        *(__nv_bfloat16*)(smem + OFF_WH2 + so) = __float2bfloat16(Wh2[k * 64 + n]);
    }
    for (int i = tid; i < 32768 / 4; i += 256)
        ((uint32_t*)(smem + OFF_H1))[i] = 0;
    {
        const int* gtok = tokens + m0 * SEQ;
        for (int i = tid; i < MROWS * SEQ; i += 256)
            stok[(i / SEQ) * TKS + (i % SEQ)] = gtok[i];
    }
    if (tid < UNITS) { sB2[tid] = b2[tid]; sWd[tid] = Wd[tid]; }
    __syncthreads();

    const uint32_t aH1 = sb + OFF_H1 + (uint32_t)(wrow * 128);
    const uint32_t aH2 = sb + OFF_H2 + (uint32_t)(wrow * 128);
    const uint32_t bW1  = sb + OFF_W1;
    const uint32_t bWX2 = sb + OFF_WX2;
    const uint32_t bWH2 = sb + OFF_WH2;

    float accA[8][4], accB[8][4];

    for (int t = 0; t < SEQ; t++) {
        // ---- stage xproj for this warp's 16 rows (2 lanes per row) ----
        {
            const int rl   = lane >> 1;
            const int half = lane & 1;
            const int tok  = stok[(wrow + rl) * TKS + t];
            const float4* src = (const float4*)(g_xproj + tok * UNITS) + half * 8;
            float4*       dst = (float4*)(xs + (wrow + rl) * XS) + half * 8;
            float4 v[8];
#pragma unroll
            for (int i = 0; i < 8; i++) v[i] = src[i];
#pragma unroll
            for (int i = 0; i < 8; i++) dst[i] = v[i];
        }

        // ---- accB = h2 @ Wh2 (prev step's h2; overlaps with GEMM1) ----
#pragma unroll
        for (int nt = 0; nt < 8; nt++)
#pragma unroll
            for (int c = 0; c < 4; c++) accB[nt][c] = 0.f;
        gemm16x64(aH2, bWH2, lane, accB);

        // ---- accA = h1 @ Wh1 ----
#pragma unroll
        for (int nt = 0; nt < 8; nt++)
#pragma unroll
            for (int c = 0; c < 4; c++) accA[nt][c] = 0.f;
        gemm16x64(aH1, bW1, lane, accA);

        __syncwarp();   // xs staged; h tiles stable for this warp

        // ---- epi1: h1 = tanh(accA + xproj) ----
        {
            const int row = wrow + gid;
#pragma unroll
            for (int nt = 0; nt < 8; nt++) {
                const int col = nt * 8 + tig * 2;
                float2 xa = *(const float2*)(xs + row * XS + col);
                float2 xb = *(const float2*)(xs + (row + 8) * XS + col);
                float h0 = tanh_fast(accA[nt][0] + xa.x);
                float h1 = tanh_fast(accA[nt][1] + xa.y);
                float h2 = tanh_fast(accA[nt][2] + xb.x);
                float h3 = tanh_fast(accA[nt][3] + xb.y);
                *(uint32_t*)(smem + OFF_H1 + SWZ(row * 128 + col * 2))       = pack_bf16(h0, h1);
                *(uint32_t*)(smem + OFF_H1 + SWZ((row + 8) * 128 + col * 2)) = pack_bf16(h2, h3);
            }
        }
        __syncwarp();   // h1 visible to own warp's ldmatrix

        // ---- accB += h1 @ Wx2 ----
        gemm16x64(aH1, bWX2, lane, accB);

        // ---- epi2: h2 = tanh(accB + b2) ----
        {
            const int row = wrow + gid;
#pragma unroll
            for (int nt = 0; nt < 8; nt++) {
                const int col = nt * 8 + tig * 2;
                float2 bb = *(const float2*)(sB2 + col);
                float h0 = tanh_fast(accB[nt][0] + bb.x);
                float h1 = tanh_fast(accB[nt][1] + bb.y);
                float h2 = tanh_fast(accB[nt][2] + bb.x);
                float h3 = tanh_fast(accB[nt][3] + bb.y);
                *(uint32_t*)(smem + OFF_H2 + SWZ(row * 128 + col * 2))       = pack_bf16(h0, h1);
                *(uint32_t*)(smem + OFF_H2 + SWZ((row + 8) * 128 + col * 2)) = pack_bf16(h2, h3);
            }
        }
        __syncwarp();   // h2 ready for next step's GEMM2a
    }

    // ---- head: out = sigmoid(h2 . Wd + bd) ----
    __syncthreads();
    if (tid < MROWS) {
        float z = 0.f;
#pragma unroll
        for (int c = 0; c < 8; c++) {
            uint4 u = *(uint4*)(smem + OFF_H2 + SWZ(tid * 128 + c * 16));
            float2 p;
            p = unpk_bf16(u.x); z += p.x * sWd[c * 8 + 0] + p.y * sWd[c * 8 + 1];
            p = unpk_bf16(u.y); z += p.x * sWd[c * 8 + 2] + p.y * sWd[c * 8 + 3];
            p = unpk_bf16(u.z); z += p.x * sWd[c * 8 + 4] + p.y * sWd[c * 8 + 5];
            p = unpk_bf16(u.w); z += p.x * sWd[c * 8 + 6] + p.y * sWd[c * 8 + 7];
        }
        out[m0 + tid] = 1.0f / (1.0f + __expf(-(z + bd[0])));
    }
}

// ---------------------------------------------------------------------------
extern "C" void kernel_launch(void* const* d_in, const int* in_sizes, int n_in,
                              void* d_out, int out_size) {
    const int*   tokens = (const int*)  d_in[0];
    const float* emb    = (const float*)d_in[1];
    const float* Wx1    = (const float*)d_in[2];
    const float* Wh1    = (const float*)d_in[3];
    const float* b1     = (const float*)d_in[4];
    const float* Wx2    = (const float*)d_in[5];
    const float* Wh2    = (const float*)d_in[6];
    const float* b2     = (const float*)d_in[7];
    const float* Wd     = (const float*)d_in[8];
    const float* bd     = (const float*)d_in[9];
    float* out = (float*)d_out;

    build_xproj_kernel<<<VOCAB / 4, 256>>>(emb, Wx1, b1);

    cudaFuncSetAttribute(rnn_mma_kernel,
                         cudaFuncAttributeMaxDynamicSharedMemorySize, SMEM_NEED);
    rnn_mma_kernel<<<BATCH / MROWS, 256, SMEM_NEED>>>(
        tokens, Wh1, Wx2, Wh2, b2, Wd, bd, out);
}

// round 5
// speedup vs baseline: 6.6618x; 1.2442x over previous
#include <cuda_runtime.h>
#include <cuda_bf16.h>
#include <cstdint>

#define VOCAB 10000
#define EMBED 100
#define SEQ   80
#define UNITS 64
#define BATCH 16384
#define MROWS 128          // batch rows per CTA
#define XS    68           // xproj smem row stride (floats)
#define TKS   81           // token smem row stride (ints)

// xproj[v][u] = b1[u] + emb[v,:] @ Wx1[:,u]   (fp32, 2.56 MB, L2-resident)
__device__ float g_xproj[VOCAB * UNITS];

// ---------------------------------------------------------------------------
// helpers
// ---------------------------------------------------------------------------
__device__ __forceinline__ uint32_t smem_u32(const void* p) {
    uint32_t a;
    asm("{ .reg .u64 t; cvta.to.shared.u64 t, %1; cvt.u32.u64 %0, t; }" : "=r"(a) : "l"(p));
    return a;
}
#define SWZ(off) ((uint32_t)(off) ^ ((((uint32_t)(off)) >> 3) & 0x70))

__device__ __forceinline__ float tanh_fast(float x) {
    float r; asm("tanh.approx.f32 %0, %1;" : "=f"(r) : "f"(x)); return r;
}
__device__ __forceinline__ uint32_t pack_bf16(float lo, float hi) {
    uint32_t r; asm("cvt.rn.bf16x2.f32 %0, %1, %2;" : "=r"(r) : "f"(hi), "f"(lo)); return r;
}
__device__ __forceinline__ float2 unpk_bf16(uint32_t u) {
    __nv_bfloat162 b = *reinterpret_cast<__nv_bfloat162*>(&u);
    return __bfloat1622float2(b);
}

#define LDSM_X4(r0, r1, r2, r3, addr)                                       \
    asm volatile("ldmatrix.sync.aligned.m8n8.x4.shared.b16 {%0,%1,%2,%3}, [%4];" \
                 : "=r"(r0), "=r"(r1), "=r"(r2), "=r"(r3) : "r"(addr))

#define MMA_BF16(ac, A, b0, b1)                                             \
    asm volatile("mma.sync.aligned.m16n8k16.row.col.f32.bf16.bf16.f32 "     \
                 "{%0,%1,%2,%3}, {%4,%5,%6,%7}, {%8,%9}, {%0,%1,%2,%3};"    \
                 : "+f"((ac)[0]), "+f"((ac)[1]), "+f"((ac)[2]), "+f"((ac)[3]) \
                 : "r"((A)[0]), "r"((A)[1]), "r"((A)[2]), "r"((A)[3]),      \
                   "r"(b0), "r"(b1))

#define PAIR_BAR(id) asm volatile("bar.sync %0, 64;" :: "r"(id) : "memory")

// ---------------------------------------------------------------------------
// Kernel A: build xproj table
// ---------------------------------------------------------------------------
__global__ void build_xproj_kernel(const float* __restrict__ emb,
                                   const float* __restrict__ Wx1,
                                   const float* __restrict__ b1) {
    __shared__ float se[4 * EMBED];
    const int v0  = blockIdx.x * 4;
    const int tid = threadIdx.x;
    for (int i = tid; i < 4 * EMBED; i += 256)
        se[i] = emb[v0 * EMBED + i];
    __syncthreads();
    const int vl = tid >> 6;
    const int u  = tid & 63;
    const float* er = se + vl * EMBED;
    float a0 = 0.f, a1 = 0.f;
#pragma unroll
    for (int e = 0; e < EMBED; e += 2) {
        a0 += er[e]     * Wx1[e * UNITS + u];
        a1 += er[e + 1] * Wx1[(e + 1) * UNITS + u];
    }
    g_xproj[(v0 + vl) * UNITS + u] = b1[u] + a0 + a1;
}

// ---------------------------------------------------------------------------
// smem layout (byte offsets from 1024-aligned base)
// ---------------------------------------------------------------------------
#define OFF_H1   0                                  // 128 x 128B bf16 (SW128)
#define OFF_H2   16384                              // 128 x 128B bf16
#define OFF_XSM  32768                              // 128 x 68 fp32
#define OFF_TOK  (OFF_XSM + MROWS * XS * 4)         // 128 x 81 int
#define OFF_B2   (OFF_TOK + MROWS * TKS * 4)
#define OFF_WD   (OFF_B2 + 256)
#define SMEM_NEED (OFF_WD + 256 + 1024)

// C[32x32] += A[32x64] @ Bfrag[64x32]; A rows folded into aBase (pair row * 128).
__device__ __forceinline__ void gemm32x32(uint32_t aBase,
                                          const uint32_t (&B)[4][4][2],
                                          int lane, float (&acc)[2][4][4]) {
    const uint32_t aRel0 = (uint32_t)((lane & 15) * 128 + (lane >> 4) * 16);
#pragma unroll
    for (int kt = 0; kt < 4; kt++) {
        uint32_t A[2][4];
#pragma unroll
        for (int mt = 0; mt < 2; mt++)
            LDSM_X4(A[mt][0], A[mt][1], A[mt][2], A[mt][3],
                    aBase + SWZ(aRel0 + (uint32_t)(mt * 2048 + kt * 32)));
#pragma unroll
        for (int mt = 0; mt < 2; mt++)
#pragma unroll
            for (int nt = 0; nt < 4; nt++)
                MMA_BF16(acc[mt][nt], A[mt], B[nt][kt][0], B[nt][kt][1]);
    }
}

// ---------------------------------------------------------------------------
// Kernel B: 4 pairs x (2 warps x 32 cols) over 32 rows each.
// Weights persistent in registers; only A-tiles + epilogue touch smem.
// ---------------------------------------------------------------------------
__global__ void __launch_bounds__(256, 1)
rnn_mma_kernel(const int*   __restrict__ tokens,
               const float* __restrict__ Wh1,
               const float* __restrict__ Wx2,
               const float* __restrict__ Wh2,
               const float* __restrict__ b2,
               const float* __restrict__ Wd,
               const float* __restrict__ bd,
               float*       __restrict__ out) {
    extern __shared__ char dynsmem[];
    char* smem = (char*)(((uintptr_t)dynsmem + 1023) & ~(uintptr_t)1023);
    const uint32_t sb = smem_u32(smem);
    float* xs   = (float*)(smem + OFF_XSM);
    int*   stok = (int*)(smem + OFF_TOK);
    float* sWd  = (float*)(smem + OFF_WD);

    const int tid  = threadIdx.x;
    const int lane = tid & 31;
    const int wid  = tid >> 5;
    const int gid  = lane >> 2;
    const int tig  = lane & 3;
    const int pair = wid >> 1;        // 0..3
    const int sub  = wid & 1;         // 0..1
    const int wrowp = pair * 32;      // pair's first row
    const int n0    = sub * 32;       // warp's first output column
    const int barid = pair + 1;
    const int m0   = blockIdx.x * MROWS;

    // ---- persistent B-fragments: [nt][kt][2], n = n0+nt*8+gid, k = kt*16+tig*2
    uint32_t B1[4][4][2], BX2[4][4][2], BH2[4][4][2];
#pragma unroll
    for (int nt = 0; nt < 4; nt++)
#pragma unroll
        for (int kt = 0; kt < 4; kt++) {
            const int n = n0 + nt * 8 + gid;
            const int k = kt * 16 + tig * 2;
            B1 [nt][kt][0] = pack_bf16(Wh1[k * 64 + n],       Wh1[(k + 1) * 64 + n]);
            B1 [nt][kt][1] = pack_bf16(Wh1[(k + 8) * 64 + n], Wh1[(k + 9) * 64 + n]);
            BX2[nt][kt][0] = pack_bf16(Wx2[k * 64 + n],       Wx2[(k + 1) * 64 + n]);
            BX2[nt][kt][1] = pack_bf16(Wx2[(k + 8) * 64 + n], Wx2[(k + 9) * 64 + n]);
            BH2[nt][kt][0] = pack_bf16(Wh2[k * 64 + n],       Wh2[(k + 1) * 64 + n]);
            BH2[nt][kt][1] = pack_bf16(Wh2[(k + 8) * 64 + n], Wh2[(k + 9) * 64 + n]);
        }
    float b2v[4][2];
#pragma unroll
    for (int nt = 0; nt < 4; nt++) {
        b2v[nt][0] = b2[n0 + nt * 8 + tig * 2];
        b2v[nt][1] = b2[n0 + nt * 8 + tig * 2 + 1];
    }

    // zero h tiles, stage tokens, vectors
    for (int i = tid; i < 32768 / 4; i += 256)
        ((uint32_t*)(smem + OFF_H1))[i] = 0;
    {
        const int* gtok = tokens + m0 * SEQ;
        for (int i = tid; i < MROWS * SEQ; i += 256)
            stok[(i / SEQ) * TKS + (i % SEQ)] = gtok[i];
    }
    if (tid < UNITS) sWd[tid] = Wd[tid];
    __syncthreads();

    const uint32_t aH1 = sb + OFF_H1 + (uint32_t)(wrowp * 128);
    const uint32_t aH2 = sb + OFF_H2 + (uint32_t)(wrowp * 128);

    float accA[2][4][4], accB[2][4][4];

    for (int t = 0; t < SEQ; t++) {
        // ---- stage xproj for this warp's 16 of the pair's 32 rows ----
        {
            const int row  = wrowp + sub * 16 + (lane >> 1);
            const int half = lane & 1;
            const int tok  = stok[row * TKS + t];
            const float4* src = (const float4*)(g_xproj + tok * UNITS) + half * 8;
            float4*       dst = (float4*)(xs + row * XS) + half * 8;
            float4 v[8];
#pragma unroll
            for (int i = 0; i < 8; i++) v[i] = src[i];
#pragma unroll
            for (int i = 0; i < 8; i++) dst[i] = v[i];
        }

        // ---- accB = h2_old @ Wh2 ; accA = h1_old @ Wh1 ----
#pragma unroll
        for (int mt = 0; mt < 2; mt++)
#pragma unroll
            for (int nt = 0; nt < 4; nt++)
#pragma unroll
                for (int c = 0; c < 4; c++) { accA[mt][nt][c] = 0.f; accB[mt][nt][c] = 0.f; }
        gemm32x32(aH2, BH2, lane, accB);
        gemm32x32(aH1, B1,  lane, accA);

        PAIR_BAR(barid);   // xs staged; both warps done reading old h1/h2

        // ---- epi1: h1 = tanh(accA + xproj) ----
#pragma unroll
        for (int mt = 0; mt < 2; mt++) {
            const int row = wrowp + mt * 16 + gid;
#pragma unroll
            for (int nt = 0; nt < 4; nt++) {
                const int col = n0 + nt * 8 + tig * 2;
                float2 xa = *(const float2*)(xs + row * XS + col);
                float2 xb = *(const float2*)(xs + (row + 8) * XS + col);
                float h0 = tanh_fast(accA[mt][nt][0] + xa.x);
                float h1 = tanh_fast(accA[mt][nt][1] + xa.y);
                float h2 = tanh_fast(accA[mt][nt][2] + xb.x);
                float h3 = tanh_fast(accA[mt][nt][3] + xb.y);
                *(uint32_t*)(smem + OFF_H1 + SWZ(row * 128 + col * 2))       = pack_bf16(h0, h1);
                *(uint32_t*)(smem + OFF_H1 + SWZ((row + 8) * 128 + col * 2)) = pack_bf16(h2, h3);
            }
        }

        PAIR_BAR(barid);   // h1_new visible to both warps of the pair

        // ---- accB += h1_new @ Wx2 ----
        gemm32x32(aH1, BX2, lane, accB);

        // ---- epi2: h2 = tanh(accB + b2) ----
#pragma unroll
        for (int mt = 0; mt < 2; mt++) {
            const int row = wrowp + mt * 16 + gid;
#pragma unroll
            for (int nt = 0; nt < 4; nt++) {
                const int col = n0 + nt * 8 + tig * 2;
                float h0 = tanh_fast(accB[mt][nt][0] + b2v[nt][0]);
                float h1 = tanh_fast(accB[mt][nt][1] + b2v[nt][1]);
                float h2 = tanh_fast(accB[mt][nt][2] + b2v[nt][0]);
                float h3 = tanh_fast(accB[mt][nt][3] + b2v[nt][1]);
                *(uint32_t*)(smem + OFF_H2 + SWZ(row * 128 + col * 2))       = pack_bf16(h0, h1);
                *(uint32_t*)(smem + OFF_H2 + SWZ((row + 8) * 128 + col * 2)) = pack_bf16(h2, h3);
            }
        }

        PAIR_BAR(barid);   // h2_new visible for next step's gemm2a
    }

    // ---- head: out = sigmoid(h2 . Wd + bd) ----
    __syncthreads();
    if (tid < MROWS) {
        float z = 0.f;
#pragma unroll
        for (int c = 0; c < 8; c++) {
            uint4 u = *(uint4*)(smem + OFF_H2 + SWZ(tid * 128 + c * 16));
            float2 p;
            p = unpk_bf16(u.x); z += p.x * sWd[c * 8 + 0] + p.y * sWd[c * 8 + 1];
            p = unpk_bf16(u.y); z += p.x * sWd[c * 8 + 2] + p.y * sWd[c * 8 + 3];
            p = unpk_bf16(u.z); z += p.x * sWd[c * 8 + 4] + p.y * sWd[c * 8 + 5];
            p = unpk_bf16(u.w); z += p.x * sWd[c * 8 + 6] + p.y * sWd[c * 8 + 7];
        }
        out[m0 + tid] = 1.0f / (1.0f + __expf(-(z + bd[0])));
    }
}

// ---------------------------------------------------------------------------
extern "C" void kernel_launch(void* const* d_in, const int* in_sizes, int n_in,
                              void* d_out, int out_size) {
    const int*   tokens = (const int*)  d_in[0];
    const float* emb    = (const float*)d_in[1];
    const float* Wx1    = (const float*)d_in[2];
    const float* Wh1    = (const float*)d_in[3];
    const float* b1     = (const float*)d_in[4];
    const float* Wx2    = (const float*)d_in[5];
    const float* Wh2    = (const float*)d_in[6];
    const float* b2     = (const float*)d_in[7];
    const float* Wd     = (const float*)d_in[8];
    const float* bd     = (const float*)d_in[9];
    float* out = (float*)d_out;

    build_xproj_kernel<<<VOCAB / 4, 256>>>(emb, Wx1, b1);

    cudaFuncSetAttribute(rnn_mma_kernel,
                         cudaFuncAttributeMaxDynamicSharedMemorySize, SMEM_NEED);
    rnn_mma_kernel<<<BATCH / MROWS, 256, SMEM_NEED>>>(
        tokens, Wh1, Wx2, Wh2, b2, Wd, bd, out);
}

// round 6
// speedup vs baseline: 8.8036x; 1.3215x over previous
#include <cuda_runtime.h>
#include <cuda_bf16.h>
#include <cstdint>

#define VOCAB 10000
#define EMBED 100
#define SEQ   80
#define UNITS 64
#define BATCH 16384
#define MROWS 128          // batch rows per CTA
#define XS    68           // xproj smem row stride (floats)
#define TKS   81           // token smem row stride (ints)

// xproj[v][u] = b1[u] + emb[v,:] @ Wx1[:,u]   (fp32, 2.56 MB, L2-resident)
__device__ float g_xproj[VOCAB * UNITS];

// ---------------------------------------------------------------------------
// helpers
// ---------------------------------------------------------------------------
__device__ __forceinline__ uint32_t smem_u32(const void* p) {
    uint32_t a;
    asm("{ .reg .u64 t; cvta.to.shared.u64 t, %1; cvt.u32.u64 %0, t; }" : "=r"(a) : "l"(p));
    return a;
}
#define SWZ(off) ((uint32_t)(off) ^ ((((uint32_t)(off)) >> 3) & 0x70))

__device__ __forceinline__ float tanh_fast(float x) {
    float r; asm("tanh.approx.f32 %0, %1;" : "=f"(r) : "f"(x)); return r;
}
__device__ __forceinline__ uint32_t pack_bf16(float lo, float hi) {
    uint32_t r; asm("cvt.rn.bf16x2.f32 %0, %1, %2;" : "=r"(r) : "f"(hi), "f"(lo)); return r;
}
__device__ __forceinline__ float2 unpk_bf16(uint32_t u) {
    __nv_bfloat162 b = *reinterpret_cast<__nv_bfloat162*>(&u);
    return __bfloat1622float2(b);
}

#define LDSM_X4(r0, r1, r2, r3, addr)                                       \
    asm volatile("ldmatrix.sync.aligned.m8n8.x4.shared.b16 {%0,%1,%2,%3}, [%4];" \
                 : "=r"(r0), "=r"(r1), "=r"(r2), "=r"(r3) : "r"(addr))

#define MMA_BF16(ac, A, b0, b1)                                             \
    asm volatile("mma.sync.aligned.m16n8k16.row.col.f32.bf16.bf16.f32 "     \
                 "{%0,%1,%2,%3}, {%4,%5,%6,%7}, {%8,%9}, {%0,%1,%2,%3};"    \
                 : "+f"((ac)[0]), "+f"((ac)[1]), "+f"((ac)[2]), "+f"((ac)[3]) \
                 : "r"((A)[0]), "r"((A)[1]), "r"((A)[2]), "r"((A)[3]),      \
                   "r"(b0), "r"(b1))

#define PAIR_BAR(id) asm volatile("bar.sync %0, 64;" :: "r"(id) : "memory")

#define CP_ASYNC_8(dst, src)                                                \
    asm volatile("cp.async.ca.shared.global [%0], [%1], 8;"                 \
                 :: "r"(dst), "l"(src) : "memory")
#define CP_COMMIT()  asm volatile("cp.async.commit_group;" ::: "memory")
#define CP_WAIT0()   asm volatile("cp.async.wait_group 0;" ::: "memory")

// ---------------------------------------------------------------------------
// Kernel A: build xproj table
// ---------------------------------------------------------------------------
__global__ void build_xproj_kernel(const float* __restrict__ emb,
                                   const float* __restrict__ Wx1,
                                   const float* __restrict__ b1) {
    __shared__ float se[4 * EMBED];
    const int v0  = blockIdx.x * 4;
    const int tid = threadIdx.x;
    for (int i = tid; i < 4 * EMBED; i += 256)
        se[i] = emb[v0 * EMBED + i];
    __syncthreads();
    const int vl = tid >> 6;
    const int u  = tid & 63;
    const float* er = se + vl * EMBED;
    float a0 = 0.f, a1 = 0.f;
#pragma unroll
    for (int e = 0; e < EMBED; e += 2) {
        a0 += er[e]     * Wx1[e * UNITS + u];
        a1 += er[e + 1] * Wx1[(e + 1) * UNITS + u];
    }
    g_xproj[(v0 + vl) * UNITS + u] = b1[u] + a0 + a1;
}

// ---------------------------------------------------------------------------
// smem layout (byte offsets from 1024-aligned base)
// ---------------------------------------------------------------------------
#define OFF_H1   0                                  // 128 x 128B bf16 (SW128)
#define OFF_H2   16384                              // 128 x 128B bf16
#define OFF_XSM  32768                              // 128 x 68 fp32
#define OFF_TOK  (OFF_XSM + MROWS * XS * 4)         // 128 x 81 int
#define OFF_B2   (OFF_TOK + MROWS * TKS * 4)
#define OFF_WD   (OFF_B2 + 256)
#define SMEM_NEED (OFF_WD + 256 + 1024)

// C[32x32] += A[32x64] @ Bfrag[64x32]; A rows folded into aBase (pair row * 128).
__device__ __forceinline__ void gemm32x32(uint32_t aBase,
                                          const uint32_t (&B)[4][4][2],
                                          int lane, float (&acc)[2][4][4]) {
    const uint32_t aRel0 = (uint32_t)((lane & 15) * 128 + (lane >> 4) * 16);
#pragma unroll
    for (int kt = 0; kt < 4; kt++) {
        uint32_t A[2][4];
#pragma unroll
        for (int mt = 0; mt < 2; mt++)
            LDSM_X4(A[mt][0], A[mt][1], A[mt][2], A[mt][3],
                    aBase + SWZ(aRel0 + (uint32_t)(mt * 2048 + kt * 32)));
#pragma unroll
        for (int mt = 0; mt < 2; mt++)
#pragma unroll
            for (int nt = 0; nt < 4; nt++)
                MMA_BF16(acc[mt][nt], A[mt], B[nt][kt][0], B[nt][kt][1]);
    }
}

// ---------------------------------------------------------------------------
// Kernel B: 4 pairs x (2 warps x 32 cols) over 32 rows each.
// Weights persistent in registers; coalesced cp.async xproj gather.
// ---------------------------------------------------------------------------
__global__ void __launch_bounds__(256, 1)
rnn_mma_kernel(const int*   __restrict__ tokens,
               const float* __restrict__ Wh1,
               const float* __restrict__ Wx2,
               const float* __restrict__ Wh2,
               const float* __restrict__ b2,
               const float* __restrict__ Wd,
               const float* __restrict__ bd,
               float*       __restrict__ out) {
    extern __shared__ char dynsmem[];
    char* smem = (char*)(((uintptr_t)dynsmem + 1023) & ~(uintptr_t)1023);
    const uint32_t sb = smem_u32(smem);
    float* xs   = (float*)(smem + OFF_XSM);
    int*   stok = (int*)(smem + OFF_TOK);
    float* sWd  = (float*)(smem + OFF_WD);

    const int tid  = threadIdx.x;
    const int lane = tid & 31;
    const int wid  = tid >> 5;
    const int gid  = lane >> 2;
    const int tig  = lane & 3;
    const int pair = wid >> 1;        // 0..3
    const int sub  = wid & 1;         // 0..1
    const int wrowp  = pair * 32;     // pair's first row
    const int wrow16 = wrowp + sub * 16;   // this warp's 16 gather rows
    const int n0    = sub * 32;       // warp's first output column
    const int barid = pair + 1;
    const int m0   = blockIdx.x * MROWS;

    // ---- persistent B-fragments: [nt][kt][2], n = n0+nt*8+gid, k = kt*16+tig*2
    uint32_t B1[4][4][2], BX2[4][4][2], BH2[4][4][2];
#pragma unroll
    for (int nt = 0; nt < 4; nt++)
#pragma unroll
        for (int kt = 0; kt < 4; kt++) {
            const int n = n0 + nt * 8 + gid;
            const int k = kt * 16 + tig * 2;
            B1 [nt][kt][0] = pack_bf16(Wh1[k * 64 + n],       Wh1[(k + 1) * 64 + n]);
            B1 [nt][kt][1] = pack_bf16(Wh1[(k + 8) * 64 + n], Wh1[(k + 9) * 64 + n]);
            BX2[nt][kt][0] = pack_bf16(Wx2[k * 64 + n],       Wx2[(k + 1) * 64 + n]);
            BX2[nt][kt][1] = pack_bf16(Wx2[(k + 8) * 64 + n], Wx2[(k + 9) * 64 + n]);
            BH2[nt][kt][0] = pack_bf16(Wh2[k * 64 + n],       Wh2[(k + 1) * 64 + n]);
            BH2[nt][kt][1] = pack_bf16(Wh2[(k + 8) * 64 + n], Wh2[(k + 9) * 64 + n]);
        }
    float b2v[4][2];
#pragma unroll
    for (int nt = 0; nt < 4; nt++) {
        b2v[nt][0] = b2[n0 + nt * 8 + tig * 2];
        b2v[nt][1] = b2[n0 + nt * 8 + tig * 2 + 1];
    }

    // zero h tiles, stage tokens, vectors
    for (int i = tid; i < 32768 / 4; i += 256)
        ((uint32_t*)(smem + OFF_H1))[i] = 0;
    {
        const int* gtok = tokens + m0 * SEQ;
        for (int i = tid; i < MROWS * SEQ; i += 256)
            stok[(i / SEQ) * TKS + (i % SEQ)] = gtok[i];
    }
    if (tid < UNITS) sWd[tid] = Wd[tid];
    __syncthreads();

    const uint32_t aH1 = sb + OFF_H1 + (uint32_t)(wrowp * 128);
    const uint32_t aH2 = sb + OFF_H2 + (uint32_t)(wrowp * 128);
    const uint32_t xsDstBase = sb + OFF_XSM + (uint32_t)(wrow16 * XS * 4) + (uint32_t)(lane * 8);

    float accA[2][4][4], accB[2][4][4];

    for (int t = 0; t < SEQ; t++) {
        // ---- coalesced async gather: 1 cp.async row per instruction,
        //      lane l carries bytes [8l, 8l+8) of that row (2 lines/instr) ----
        {
            int tokreg = 0;
            if (lane < 16) tokreg = stok[(wrow16 + lane) * TKS + t];
#pragma unroll
            for (int r = 0; r < 16; r++) {
                const int tok = __shfl_sync(0xffffffffu, tokreg, r);
                const float* src = g_xproj + tok * UNITS + lane * 2;
                CP_ASYNC_8(xsDstBase + (uint32_t)(r * XS * 4), src);
            }
            CP_COMMIT();
        }

        // ---- accB = h2_old @ Wh2 ; accA = h1_old @ Wh1 ----
#pragma unroll
        for (int mt = 0; mt < 2; mt++)
#pragma unroll
            for (int nt = 0; nt < 4; nt++)
#pragma unroll
                for (int c = 0; c < 4; c++) { accA[mt][nt][c] = 0.f; accB[mt][nt][c] = 0.f; }
        gemm32x32(aH2, BH2, lane, accB);
        gemm32x32(aH1, B1,  lane, accA);

        CP_WAIT0();        // my 16 xs rows landed
        PAIR_BAR(barid);   // partner's xs rows landed; old h reads complete

        // ---- epi1: h1 = tanh(accA + xproj) ----
#pragma unroll
        for (int mt = 0; mt < 2; mt++) {
            const int row = wrowp + mt * 16 + gid;
#pragma unroll
            for (int nt = 0; nt < 4; nt++) {
                const int col = n0 + nt * 8 + tig * 2;
                float2 xa = *(const float2*)(xs + row * XS + col);
                float2 xb = *(const float2*)(xs + (row + 8) * XS + col);
                float h0 = tanh_fast(accA[mt][nt][0] + xa.x);
                float h1 = tanh_fast(accA[mt][nt][1] + xa.y);
                float h2 = tanh_fast(accA[mt][nt][2] + xb.x);
                float h3 = tanh_fast(accA[mt][nt][3] + xb.y);
                *(uint32_t*)(smem + OFF_H1 + SWZ(row * 128 + col * 2))       = pack_bf16(h0, h1);
                *(uint32_t*)(smem + OFF_H1 + SWZ((row + 8) * 128 + col * 2)) = pack_bf16(h2, h3);
            }
        }

        PAIR_BAR(barid);   // h1_new visible to both warps of the pair

        // ---- accB += h1_new @ Wx2 ----
        gemm32x32(aH1, BX2, lane, accB);

        // ---- epi2: h2 = tanh(accB + b2) ----
#pragma unroll
        for (int mt = 0; mt < 2; mt++) {
            const int row = wrowp + mt * 16 + gid;
#pragma unroll
            for (int nt = 0; nt < 4; nt++) {
                const int col = n0 + nt * 8 + tig * 2;
                float h0 = tanh_fast(accB[mt][nt][0] + b2v[nt][0]);
                float h1 = tanh_fast(accB[mt][nt][1] + b2v[nt][1]);
                float h2 = tanh_fast(accB[mt][nt][2] + b2v[nt][0]);
                float h3 = tanh_fast(accB[mt][nt][3] + b2v[nt][1]);
                *(uint32_t*)(smem + OFF_H2 + SWZ(row * 128 + col * 2))       = pack_bf16(h0, h1);
                *(uint32_t*)(smem + OFF_H2 + SWZ((row + 8) * 128 + col * 2)) = pack_bf16(h2, h3);
            }
        }

        PAIR_BAR(barid);   // h2_new visible for next step's gemm2a
    }

    // ---- head: out = sigmoid(h2 . Wd + bd) ----
    __syncthreads();
    if (tid < MROWS) {
        float z = 0.f;
#pragma unroll
        for (int c = 0; c < 8; c++) {
            uint4 u = *(uint4*)(smem + OFF_H2 + SWZ(tid * 128 + c * 16));
            float2 p;
            p = unpk_bf16(u.x); z += p.x * sWd[c * 8 + 0] + p.y * sWd[c * 8 + 1];
            p = unpk_bf16(u.y); z += p.x * sWd[c * 8 + 2] + p.y * sWd[c * 8 + 3];
            p = unpk_bf16(u.z); z += p.x * sWd[c * 8 + 4] + p.y * sWd[c * 8 + 5];
            p = unpk_bf16(u.w); z += p.x * sWd[c * 8 + 6] + p.y * sWd[c * 8 + 7];
        }
        out[m0 + tid] = 1.0f / (1.0f + __expf(-(z + bd[0])));
    }
}

// ---------------------------------------------------------------------------
extern "C" void kernel_launch(void* const* d_in, const int* in_sizes, int n_in,
                              void* d_out, int out_size) {
    const int*   tokens = (const int*)  d_in[0];
    const float* emb    = (const float*)d_in[1];
    const float* Wx1    = (const float*)d_in[2];
    const float* Wh1    = (const float*)d_in[3];
    const float* b1     = (const float*)d_in[4];
    const float* Wx2    = (const float*)d_in[5];
    const float* Wh2    = (const float*)d_in[6];
    const float* b2     = (const float*)d_in[7];
    const float* Wd     = (const float*)d_in[8];
    const float* bd     = (const float*)d_in[9];
    float* out = (float*)d_out;

    build_xproj_kernel<<<VOCAB / 4, 256>>>(emb, Wx1, b1);

    cudaFuncSetAttribute(rnn_mma_kernel,
                         cudaFuncAttributeMaxDynamicSharedMemorySize, SMEM_NEED);
    rnn_mma_kernel<<<BATCH / MROWS, 256, SMEM_NEED>>>(
        tokens, Wh1, Wx2, Wh2, b2, Wd, bd, out);
}

// round 7
// speedup vs baseline: 10.5071x; 1.1935x over previous
#include <cuda_runtime.h>
#include <cuda_bf16.h>
#include <cstdint>

#define VOCAB 10000
#define EMBED 100
#define SEQ   80
#define UNITS 64
#define BATCH 16384
#define MROWS 128          // batch rows per CTA
#define XS    68           // xproj smem row stride (floats)
#define TKS   81           // token smem row stride (ints)

// xproj[v][u] = b1[u] + emb[v,:] @ Wx1[:,u]   (fp32, 2.56 MB, L2-resident)
__device__ float g_xproj[VOCAB * UNITS];

// ---------------------------------------------------------------------------
// helpers
// ---------------------------------------------------------------------------
__device__ __forceinline__ uint32_t smem_u32(const void* p) {
    uint32_t a;
    asm("{ .reg .u64 t; cvta.to.shared.u64 t, %1; cvt.u32.u64 %0, t; }" : "=r"(a) : "l"(p));
    return a;
}
#define SWZ(off) ((uint32_t)(off) ^ ((((uint32_t)(off)) >> 3) & 0x70))

__device__ __forceinline__ float tanh_fast(float x) {
    float r; asm("tanh.approx.f32 %0, %1;" : "=f"(r) : "f"(x)); return r;
}
__device__ __forceinline__ uint32_t pack_bf16(float lo, float hi) {
    uint32_t r; asm("cvt.rn.bf16x2.f32 %0, %1, %2;" : "=r"(r) : "f"(hi), "f"(lo)); return r;
}
__device__ __forceinline__ float2 unpk_bf16(uint32_t u) {
    __nv_bfloat162 b = *reinterpret_cast<__nv_bfloat162*>(&u);
    return __bfloat1622float2(b);
}

#define LDSM_X4(r0, r1, r2, r3, addr)                                       \
    asm volatile("ldmatrix.sync.aligned.m8n8.x4.shared.b16 {%0,%1,%2,%3}, [%4];" \
                 : "=r"(r0), "=r"(r1), "=r"(r2), "=r"(r3) : "r"(addr))

#define MMA_BF16(ac, A, b0, b1)                                             \
    asm volatile("mma.sync.aligned.m16n8k16.row.col.f32.bf16.bf16.f32 "     \
                 "{%0,%1,%2,%3}, {%4,%5,%6,%7}, {%8,%9}, {%0,%1,%2,%3};"    \
                 : "+f"((ac)[0]), "+f"((ac)[1]), "+f"((ac)[2]), "+f"((ac)[3]) \
                 : "r"((A)[0]), "r"((A)[1]), "r"((A)[2]), "r"((A)[3]),      \
                   "r"(b0), "r"(b1))

#define CP_ASYNC_8(dst, src)                                                \
    asm volatile("cp.async.ca.shared.global [%0], [%1], 8;"                 \
                 :: "r"(dst), "l"(src) : "memory")
#define CP_COMMIT()  asm volatile("cp.async.commit_group;" ::: "memory")
#define CP_WAIT0()   asm volatile("cp.async.wait_group 0;" ::: "memory")

// ---------------------------------------------------------------------------
// Kernel A: build xproj table
// ---------------------------------------------------------------------------
__global__ void build_xproj_kernel(const float* __restrict__ emb,
                                   const float* __restrict__ Wx1,
                                   const float* __restrict__ b1) {
    __shared__ float se[4 * EMBED];
    const int v0  = blockIdx.x * 4;
    const int tid = threadIdx.x;
    for (int i = tid; i < 4 * EMBED; i += 256)
        se[i] = emb[v0 * EMBED + i];
    __syncthreads();
    const int vl = tid >> 6;
    const int u  = tid & 63;
    const float* er = se + vl * EMBED;
    float a0 = 0.f, a1 = 0.f;
#pragma unroll
    for (int e = 0; e < EMBED; e += 2) {
        a0 += er[e]     * Wx1[e * UNITS + u];
        a1 += er[e + 1] * Wx1[(e + 1) * UNITS + u];
    }
    g_xproj[(v0 + vl) * UNITS + u] = b1[u] + a0 + a1;
}

// ---------------------------------------------------------------------------
// smem layout (byte offsets from 1024-aligned base)
// ---------------------------------------------------------------------------
#define OFF_W1   0                                  // Wh1^T [n][k] bf16 SW128, 8KB
#define OFF_XS0  8192                               // xproj buf 0: 128 x 68 fp32
#define OFF_XS1  (OFF_XS0 + MROWS * XS * 4)         // xproj buf 1
#define OFF_TOK  (OFF_XS1 + MROWS * XS * 4)         // 128 x 81 int
#define OFF_B2   (OFF_TOK + MROWS * TKS * 4)
#define OFF_WD   (OFF_B2 + 256)
#define SMEM_NEED (OFF_WD + 256 + 1024)

// ---------------------------------------------------------------------------
// Kernel B: 8 independent warps x 16 rows x full 64 cols.
// h1/h2 live in registers as MMA fragments (C-frag == A-frag identity).
// BX2/BH2 persistent register B-frags; Wh1 streamed via ldmatrix.
// ZERO barriers and zero smem h-traffic in the 80-step loop.
// ---------------------------------------------------------------------------
__global__ void __launch_bounds__(256, 1)
rnn_mma_kernel(const int*   __restrict__ tokens,
               const float* __restrict__ Wh1,
               const float* __restrict__ Wx2,
               const float* __restrict__ Wh2,
               const float* __restrict__ b2,
               const float* __restrict__ Wd,
               const float* __restrict__ bd,
               float*       __restrict__ out) {
    extern __shared__ char dynsmem[];
    char* smem = (char*)(((uintptr_t)dynsmem + 1023) & ~(uintptr_t)1023);
    const uint32_t sb = smem_u32(smem);
    int*   stok = (int*)(smem + OFF_TOK);
    float* sB2  = (float*)(smem + OFF_B2);
    float* sWd  = (float*)(smem + OFF_WD);

    const int tid  = threadIdx.x;
    const int lane = tid & 31;
    const int wid  = tid >> 5;
    const int gid  = lane >> 2;
    const int tig  = lane & 3;
    const int wrow16 = wid * 16;          // this warp's 16 rows
    const int m0   = blockIdx.x * MROWS;

    // ---- persistent B-fragments (full 64 cols): [nt][kt][2] ----
    uint32_t BX2[8][4][2], BH2[8][4][2];
#pragma unroll
    for (int nt = 0; nt < 8; nt++)
#pragma unroll
        for (int kt = 0; kt < 4; kt++) {
            const int n = nt * 8 + gid;
            const int k = kt * 16 + tig * 2;
            BX2[nt][kt][0] = pack_bf16(Wx2[k * 64 + n],       Wx2[(k + 1) * 64 + n]);
            BX2[nt][kt][1] = pack_bf16(Wx2[(k + 8) * 64 + n], Wx2[(k + 9) * 64 + n]);
            BH2[nt][kt][0] = pack_bf16(Wh2[k * 64 + n],       Wh2[(k + 1) * 64 + n]);
            BH2[nt][kt][1] = pack_bf16(Wh2[(k + 8) * 64 + n], Wh2[(k + 9) * 64 + n]);
        }

    // ---- init smem: Wh1^T tile [n][k] bf16 SW128, tokens, b2, Wd ----
    for (int i = tid; i < UNITS * UNITS; i += 256) {
        int n = i >> 6, k = i & 63;
        *(__nv_bfloat16*)(smem + OFF_W1 + SWZ(n * 128 + k * 2)) =
            __float2bfloat16(Wh1[k * 64 + n]);
    }
    {
        const int* gtok = tokens + m0 * SEQ;
        for (int i = tid; i < MROWS * SEQ; i += 256)
            stok[(i / SEQ) * TKS + (i % SEQ)] = gtok[i];
    }
    if (tid < UNITS) { sB2[tid] = b2[tid]; sWd[tid] = Wd[tid]; }
    __syncthreads();

    const uint32_t w1Base = sb + OFF_W1;
    const uint32_t bRow = (uint32_t)((((lane >> 4) << 3) | (lane & 7)));
    const uint32_t bKo  = (uint32_t)(((lane >> 3) & 1) << 3);

    // h fragments (A-frag layout), h0 = 0
    uint32_t h1f[4][4], h2f[4][4];
#pragma unroll
    for (int kt = 0; kt < 4; kt++)
#pragma unroll
        for (int j = 0; j < 4; j++) { h1f[kt][j] = 0u; h2f[kt][j] = 0u; }

    float acc1[8][4], acc2[8][4];

    for (int t = 0; t < SEQ; t++) {
        float* xs = (float*)(smem + ((t & 1) ? OFF_XS1 : OFF_XS0));
        const uint32_t xsDst = sb + ((t & 1) ? OFF_XS1 : OFF_XS0)
                             + (uint32_t)(wrow16 * XS * 4) + (uint32_t)(lane * 8);

        // ---- coalesced async xproj gather for this warp's 16 rows ----
        {
            int tokreg = 0;
            if (lane < 16) tokreg = stok[(wrow16 + lane) * TKS + t];
#pragma unroll
            for (int r = 0; r < 16; r++) {
                const int tok = __shfl_sync(0xffffffffu, tokreg, r);
                CP_ASYNC_8(xsDst + (uint32_t)(r * XS * 4), g_xproj + tok * UNITS + lane * 2);
            }
            CP_COMMIT();
        }

        // ---- gemm1 (h1 @ Wh1, B streamed) interleaved with gemm2a (h2 @ Wh2, regs) ----
#pragma unroll
        for (int nt = 0; nt < 8; nt++)
#pragma unroll
            for (int c = 0; c < 4; c++) { acc1[nt][c] = 0.f; acc2[nt][c] = 0.f; }
#pragma unroll
        for (int kt = 0; kt < 4; kt++) {
            uint32_t Bs[4][4];
#pragma unroll
            for (int np = 0; np < 4; np++)
                LDSM_X4(Bs[np][0], Bs[np][1], Bs[np][2], Bs[np][3],
                        w1Base + SWZ((np * 16 + bRow) * 128 + (kt * 16 + bKo) * 2));
            // independent reg-only MMAs hide the LDSM latency
#pragma unroll
            for (int nt = 0; nt < 8; nt++)
                MMA_BF16(acc2[nt], h2f[kt], BH2[nt][kt][0], BH2[nt][kt][1]);
#pragma unroll
            for (int np = 0; np < 4; np++) {
                MMA_BF16(acc1[2 * np],     h1f[kt], Bs[np][0], Bs[np][1]);
                MMA_BF16(acc1[2 * np + 1], h1f[kt], Bs[np][2], Bs[np][3]);
            }
        }

        CP_WAIT0();   // xproj rows landed (own warp's only — no barrier needed)

        // ---- epi1: h1 = tanh(acc1 + xproj), repacked directly as A-frags ----
        {
            const int r0 = wrow16 + gid;
#pragma unroll
            for (int nt = 0; nt < 8; nt++) {
                const int col = nt * 8 + tig * 2;
                float2 xa = *(const float2*)(xs + r0 * XS + col);
                float2 xb = *(const float2*)(xs + (r0 + 8) * XS + col);
                float h0 = tanh_fast(acc1[nt][0] + xa.x);
                float h1 = tanh_fast(acc1[nt][1] + xa.y);
                float h2 = tanh_fast(acc1[nt][2] + xb.x);
                float h3 = tanh_fast(acc1[nt][3] + xb.y);
                h1f[nt >> 1][(nt & 1) * 2 + 0] = pack_bf16(h0, h1);   // row gid
                h1f[nt >> 1][(nt & 1) * 2 + 1] = pack_bf16(h2, h3);   // row gid+8
            }
        }

        // ---- gemm2b: acc2 += h1_new @ Wx2 (all registers) ----
#pragma unroll
        for (int kt = 0; kt < 4; kt++)
#pragma unroll
            for (int nt = 0; nt < 8; nt++)
                MMA_BF16(acc2[nt], h1f[kt], BX2[nt][kt][0], BX2[nt][kt][1]);

        // ---- epi2: h2 = tanh(acc2 + b2), repacked as A-frags ----
#pragma unroll
        for (int nt = 0; nt < 8; nt++) {
            const int col = nt * 8 + tig * 2;
            float2 bb = *(const float2*)(sB2 + col);
            float h0 = tanh_fast(acc2[nt][0] + bb.x);
            float h1 = tanh_fast(acc2[nt][1] + bb.y);
            float h2 = tanh_fast(acc2[nt][2] + bb.x);
            float h3 = tanh_fast(acc2[nt][3] + bb.y);
            h2f[nt >> 1][(nt & 1) * 2 + 0] = pack_bf16(h0, h1);
            h2f[nt >> 1][(nt & 1) * 2 + 1] = pack_bf16(h2, h3);
        }
    }

    // ---- head: out = sigmoid(h2 . Wd + bd); reduce over tig group ----
    float z0 = 0.f, z1 = 0.f;
#pragma unroll
    for (int nt = 0; nt < 8; nt++) {
        const int col = nt * 8 + tig * 2;
        float2 wd = *(const float2*)(sWd + col);
        float2 a = unpk_bf16(h2f[nt >> 1][(nt & 1) * 2 + 0]);   // row gid
        float2 b = unpk_bf16(h2f[nt >> 1][(nt & 1) * 2 + 1]);   // row gid+8
        z0 += a.x * wd.x + a.y * wd.y;
        z1 += b.x * wd.x + b.y * wd.y;
    }
    z0 += __shfl_xor_sync(0xffffffffu, z0, 1);
    z0 += __shfl_xor_sync(0xffffffffu, z0, 2);
    z1 += __shfl_xor_sync(0xffffffffu, z1, 1);
    z1 += __shfl_xor_sync(0xffffffffu, z1, 2);
    if (tig == 0) {
        const float bd0 = bd[0];
        out[m0 + wrow16 + gid]     = 1.0f / (1.0f + __expf(-(z0 + bd0)));
        out[m0 + wrow16 + gid + 8] = 1.0f / (1.0f + __expf(-(z1 + bd0)));
    }
}

// ---------------------------------------------------------------------------
extern "C" void kernel_launch(void* const* d_in, const int* in_sizes, int n_in,
                              void* d_out, int out_size) {
    const int*   tokens = (const int*)  d_in[0];
    const float* emb    = (const float*)d_in[1];
    const float* Wx1    = (const float*)d_in[2];
    const float* Wh1    = (const float*)d_in[3];
    const float* b1     = (const float*)d_in[4];
    const float* Wx2    = (const float*)d_in[5];
    const float* Wh2    = (const float*)d_in[6];
    const float* b2     = (const float*)d_in[7];
    const float* Wd     = (const float*)d_in[8];
    const float* bd     = (const float*)d_in[9];
    float* out = (float*)d_out;

    build_xproj_kernel<<<VOCAB / 4, 256>>>(emb, Wx1, b1);

    cudaFuncSetAttribute(rnn_mma_kernel,
                         cudaFuncAttributeMaxDynamicSharedMemorySize, SMEM_NEED);
    rnn_mma_kernel<<<BATCH / MROWS, 256, SMEM_NEED>>>(
        tokens, Wh1, Wx2, Wh2, b2, Wd, bd, out);
}